// round 3
// baseline (speedup 1.0000x reference)
#include <cuda_runtime.h>
#include <math_constants.h>

#define L     8192
#define D     64
#define BM    64
#define NCH   8
#define CHUNK 1024          // L / NCH
#define BN1   128           // pass1 key-tile width
#define T1    (CHUNK/BN1)   // 8 tiles per chunk (pass1)
#define BN2   64            // pass2 key-tile width
#define T2    (CHUNK/BN2)   // 16 tiles per chunk (pass2)
#define NT    256

// Scratch (allocation-free rule: __device__ globals)
__device__ float g_mp[NCH * L];            // per-chunk partial row max
__device__ float g_lp[NCH * L];            // per-chunk partial sum-of-exp
__device__ float g_m[L];                   // final row max
__device__ float g_li[L];                  // final 1/l
__device__ float g_opart[(size_t)NCH * L * D];  // per-chunk partial O (16 MB)

// ---------------------------------------------------------------------------
// Pass 1: raw S = Q K^T for a 64-row x 1024-col strip + per-chunk m/l stats.
// Thread layout: 8 warps, warp w owns rows r0 = w*8 .. w*8+7 (q reads are
// broadcasts, stats reduce fully inside the warp). Lane tx owns 4 columns.
// ---------------------------------------------------------------------------
__global__ __launch_bounds__(NT) void pass1_kernel(const float* __restrict__ Q,
                                                   const float* __restrict__ Km,
                                                   float* __restrict__ S) {
    __shared__ float sQt[D][BM + 4];   // transposed, +4 pad keeps float4 align
    __shared__ float sKt[D][BN1 + 4];

    const int tid = threadIdx.x;
    const int tx  = tid & 31;
    const int wid = tid >> 5;
    const int r0  = wid * 8;
    const int c0  = tx * 4;
    const int rowblk  = blockIdx.y * BM;
    const int colbase = blockIdx.x * CHUNK;

    for (int idx = tid; idx < BM * D; idx += NT) {
        const int r = idx >> 6;
        const int d = idx & 63;
        sQt[d][r] = Q[(rowblk + r) * D + d];
    }

    float m[8], l[8];
#pragma unroll
    for (int i = 0; i < 8; i++) { m[i] = -CUDART_INF_F; l[i] = 0.0f; }
    __syncthreads();

    for (int t = 0; t < T1; t++) {
        const int kb = colbase + t * BN1;
        for (int idx = tid; idx < BN1 * D; idx += NT) {
            const int c = idx >> 6;
            const int d = idx & 63;
            sKt[d][c] = Km[(size_t)(kb + c) * D + d];
        }
        __syncthreads();

        float acc[8][4];
#pragma unroll
        for (int i = 0; i < 8; i++)
#pragma unroll
            for (int j = 0; j < 4; j++) acc[i][j] = 0.0f;

#pragma unroll 8
        for (int d = 0; d < D; d++) {
            const float4 q0 = *reinterpret_cast<const float4*>(&sQt[d][r0]);
            const float4 q1 = *reinterpret_cast<const float4*>(&sQt[d][r0 + 4]);
            const float4 kf = *reinterpret_cast<const float4*>(&sKt[d][c0]);
            const float qa[8] = {q0.x, q0.y, q0.z, q0.w, q1.x, q1.y, q1.z, q1.w};
            const float ka[4] = {kf.x, kf.y, kf.z, kf.w};
#pragma unroll
            for (int i = 0; i < 8; i++)
#pragma unroll
                for (int j = 0; j < 4; j++)
                    acc[i][j] = fmaf(qa[i], ka[j], acc[i][j]);
        }

        // Raw logits out (pass2 overwrites with normalized softmax)
#pragma unroll
        for (int i = 0; i < 8; i++) {
            *reinterpret_cast<float4*>(
                &S[(size_t)(rowblk + r0 + i) * L + kb + c0]) =
                make_float4(acc[i][0], acc[i][1], acc[i][2], acc[i][3]);
        }

        // Per-thread online stats over this thread's 4 columns
#pragma unroll
        for (int i = 0; i < 8; i++) {
            const float mx = fmaxf(fmaxf(acc[i][0], acc[i][1]),
                                   fmaxf(acc[i][2], acc[i][3]));
            const float nm = fmaxf(m[i], mx);
            l[i] = l[i] * __expf(m[i] - nm) +
                   __expf(acc[i][0] - nm) + __expf(acc[i][1] - nm) +
                   __expf(acc[i][2] - nm) + __expf(acc[i][3] - nm);
            m[i] = nm;
        }
        __syncthreads();
    }

    // Warp-level combine of the 32 per-lane (m,l) pairs for each owned row
#pragma unroll
    for (int i = 0; i < 8; i++) {
        float mi = m[i], li = l[i];
#pragma unroll
        for (int off = 16; off; off >>= 1) {
            const float om = __shfl_xor_sync(0xffffffffu, mi, off);
            const float ol = __shfl_xor_sync(0xffffffffu, li, off);
            const float nm = fmaxf(mi, om);
            li = li * __expf(mi - nm) + ol * __expf(om - nm);
            mi = nm;
        }
        if (tx == 0) {
            g_mp[blockIdx.x * L + rowblk + r0 + i] = mi;
            g_lp[blockIdx.x * L + rowblk + r0 + i] = li;
        }
    }
}

// ---------------------------------------------------------------------------
// Combine per-chunk stats into final per-row (m, 1/l)
// ---------------------------------------------------------------------------
__global__ void combine_kernel() {
    const int row = blockIdx.x * 256 + threadIdx.x;
    float m = -CUDART_INF_F;
#pragma unroll
    for (int c = 0; c < NCH; c++) m = fmaxf(m, g_mp[c * L + row]);
    float l = 0.0f;
#pragma unroll
    for (int c = 0; c < NCH; c++)
        l += g_lp[c * L + row] * __expf(g_mp[c * L + row] - m);
    g_m[row]  = m;
    g_li[row] = 1.0f / l;
}

// ---------------------------------------------------------------------------
// Pass 2: normalize raw logits in place + partial O for this chunk
// ---------------------------------------------------------------------------
__global__ __launch_bounds__(NT) void pass2_kernel(const float* __restrict__ V,
                                                   float* __restrict__ S) {
    __shared__ float sP[BM][BN2];
    __shared__ float sV[BN2][D];
    __shared__ float m_s[BM], li_s[BM];

    const int tid = threadIdx.x;
    const int tx  = tid & 15;
    const int ty  = tid >> 4;
    const int r0  = ty * 4;
    const int c0  = tx * 4;
    const int d0  = tx * 4;
    const int rowblk  = blockIdx.y * BM;
    const int colbase = blockIdx.x * CHUNK;

    if (tid < BM) {
        m_s[tid]  = g_m[rowblk + tid];
        li_s[tid] = g_li[rowblk + tid];
    }

    float acc[4][4];
#pragma unroll
    for (int i = 0; i < 4; i++)
#pragma unroll
        for (int j = 0; j < 4; j++) acc[i][j] = 0.0f;

    __syncthreads();

    for (int t = 0; t < T2; t++) {
        const int kb = colbase + t * BN2;
        {
            const float4* vsrc = reinterpret_cast<const float4*>(V + (size_t)kb * D);
            float4*       vdst = reinterpret_cast<float4*>(&sV[0][0]);
            for (int idx = tid; idx < BN2 * D / 4; idx += NT) vdst[idx] = vsrc[idx];
        }

#pragma unroll
        for (int i = 0; i < 4; i++) {
            float* srow = &S[(size_t)(rowblk + r0 + i) * L + kb + c0];
            float4 s4 = *reinterpret_cast<const float4*>(srow);
            const float mi = m_s[r0 + i];
            const float sc = li_s[r0 + i];
            float4 p4;
            p4.x = __expf(s4.x - mi) * sc;
            p4.y = __expf(s4.y - mi) * sc;
            p4.z = __expf(s4.z - mi) * sc;
            p4.w = __expf(s4.w - mi) * sc;
            *reinterpret_cast<float4*>(srow) = p4;
            *reinterpret_cast<float4*>(&sP[r0 + i][c0]) = p4;
        }
        __syncthreads();

#pragma unroll 4
        for (int c = 0; c < BN2; c++) {
            const float4 vf = *reinterpret_cast<const float4*>(&sV[c][d0]);
            const float va[4] = {vf.x, vf.y, vf.z, vf.w};
            float pa[4];
#pragma unroll
            for (int i = 0; i < 4; i++) pa[i] = sP[r0 + i][c];
#pragma unroll
            for (int i = 0; i < 4; i++)
#pragma unroll
                for (int j = 0; j < 4; j++)
                    acc[i][j] = fmaf(pa[i], va[j], acc[i][j]);
        }
        __syncthreads();
    }

    float* op = g_opart + ((size_t)blockIdx.x * L + rowblk) * D;
#pragma unroll
    for (int i = 0; i < 4; i++) {
        *reinterpret_cast<float4*>(&op[(r0 + i) * D + d0]) =
            make_float4(acc[i][0], acc[i][1], acc[i][2], acc[i][3]);
    }
}

// ---------------------------------------------------------------------------
// Reduce the NCH partial O buffers into the final O
// ---------------------------------------------------------------------------
__global__ void reduce_o_kernel(float* __restrict__ O) {
    const size_t idx = (size_t)blockIdx.x * 256 + threadIdx.x;   // float4 index
    float4 s = make_float4(0.f, 0.f, 0.f, 0.f);
#pragma unroll
    for (int c = 0; c < NCH; c++) {
        const float4 v = *reinterpret_cast<const float4*>(
            &g_opart[(size_t)c * L * D + idx * 4]);
        s.x += v.x; s.y += v.y; s.z += v.z; s.w += v.w;
    }
    *reinterpret_cast<float4*>(&O[idx * 4]) = s;
}

extern "C" void kernel_launch(void* const* d_in, const int* in_sizes, int n_in,
                              void* d_out, int out_size) {
    const float* q = (const float*)d_in[0];
    const float* k = (const float*)d_in[1];
    const float* v = (const float*)d_in[2];

    float* out   = (float*)d_out;          // [L, D]
    float* score = out + (size_t)L * D;    // [L, L]

    dim3 grid(NCH, L / BM);
    pass1_kernel<<<grid, NT>>>(q, k, score);
    combine_kernel<<<L / 256, 256>>>();
    pass2_kernel<<<grid, NT>>>(v, score);
    reduce_o_kernel<<<(L * D / 4) / 256, 256>>>(out);
}

// round 5
// speedup vs baseline: 1.2496x; 1.2496x over previous
#include <cuda_runtime.h>
#include <cuda_bf16.h>
#include <math_constants.h>
#include <cstdint>

#define L     8192
#define D     64
#define BM    128            // query rows per CTA
#define NCH   8
#define CHUNK 1024           // L / NCH
#define BN1   128            // pass1 key-tile width
#define T1    8              // CHUNK / BN1
#define BN2   64             // pass2 key-tile width
#define T2    16             // CHUNK / BN2
#define NT    256
#define PADE  72             // padded row length in bf16 elems
#define ROWB  144            // padded row length in bytes (72*2)

// ---------------- scratch (__device__ globals; no allocation allowed) -------
__device__ float g_mp[NCH * L];
__device__ float g_lp[NCH * L];
__device__ float g_m[L];
__device__ float g_li[L];
__device__ float g_opart[(size_t)NCH * L * D];   // 16 MB partial O

// ---------------- helpers ---------------------------------------------------
__device__ __forceinline__ uint32_t smem_to_u32(const void* p) {
    uint32_t a;
    asm("{ .reg .u64 t; cvta.to.shared.u64 t, %1; cvt.u32.u64 %0, t; }"
        : "=r"(a) : "l"(p));
    return a;
}
__device__ __forceinline__ void ldsm_x4(uint32_t* r, uint32_t a) {
    asm volatile("ldmatrix.sync.aligned.m8n8.x4.shared.b16 {%0,%1,%2,%3}, [%4];"
                 : "=r"(r[0]), "=r"(r[1]), "=r"(r[2]), "=r"(r[3]) : "r"(a));
}
__device__ __forceinline__ void ldsm_x4_t(uint32_t* r, uint32_t a) {
    asm volatile("ldmatrix.sync.aligned.m8n8.x4.trans.shared.b16 {%0,%1,%2,%3}, [%4];"
                 : "=r"(r[0]), "=r"(r[1]), "=r"(r[2]), "=r"(r[3]) : "r"(a));
}
__device__ __forceinline__ void mma_bf16(float* c, const uint32_t* a,
                                         uint32_t b0, uint32_t b1) {
    asm volatile("mma.sync.aligned.m16n8k16.row.col.f32.bf16.bf16.f32 "
                 "{%0,%1,%2,%3}, {%4,%5,%6,%7}, {%8,%9}, {%0,%1,%2,%3};"
                 : "+f"(c[0]), "+f"(c[1]), "+f"(c[2]), "+f"(c[3])
                 : "r"(a[0]), "r"(a[1]), "r"(a[2]), "r"(a[3]), "r"(b0), "r"(b1));
}
__device__ __forceinline__ void split2(float x, float y,
                                       __nv_bfloat162& h2, __nv_bfloat162& l2) {
    __nv_bfloat16 hx = __float2bfloat16(x);
    __nv_bfloat16 hy = __float2bfloat16(y);
    h2.x = hx; h2.y = hy;
    l2.x = __float2bfloat16(x - __bfloat162float(hx));
    l2.y = __float2bfloat16(y - __bfloat162float(hy));
}

// pass1 smem byte offsets
#define SQH 0
#define SQL 18432
#define SKH 36864
#define SKL 55296
#define P1_STATS 73728
#define P1_SMEM  76800
// pass2 smem byte offsets
#define SPH 0
#define SPL 18432
#define SVH 36864
#define SVL 46080
#define P2_STATS 55296
#define P2_SMEM  56320

// ---------------------------------------------------------------------------
// Pass 1: S = Q K^T raw logits (mma.sync, 2-limb bf16) + per-chunk (m,l)
// warps: 4 row-groups x 2 col-groups; warp tile 32x64
// ---------------------------------------------------------------------------
__global__ __launch_bounds__(NT, 2) void pass1_kernel(const float* __restrict__ Q,
                                                      const float* __restrict__ Km,
                                                      float* __restrict__ S) {
    extern __shared__ char smem[];
    const uint32_t sb = smem_to_u32(smem);
    const int tid  = threadIdx.x;
    const int lane = tid & 31;
    const int w    = tid >> 5;
    const int wr   = (w & 3) * 32;
    const int wc   = (w >> 2) * 64;
    const int cg   = w >> 2;
    const int rowblk  = blockIdx.y * BM;
    const int colbase = blockIdx.x * CHUNK;

    float* row_m = (float*)(smem + P1_STATS);       // [128]
    float* row_l = row_m + 128;                     // [128]
    float* pm    = row_l + 128;                     // [2][128]
    float* pl    = pm + 256;                        // [2][128]

    // Q tile -> 2-limb bf16 (one warp per row per pass => conflict-free)
    for (int idx = tid; idx < BM * 32; idx += NT) {
        const int r = idx >> 5, d2 = idx & 31;
        const float2 v = *(const float2*)&Q[(size_t)(rowblk + r) * D + d2 * 2];
        __nv_bfloat162 h2, l2; split2(v.x, v.y, h2, l2);
        *(__nv_bfloat162*)(smem + SQH + r * ROWB + d2 * 4) = h2;
        *(__nv_bfloat162*)(smem + SQL + r * ROWB + d2 * 4) = l2;
    }
    if (tid < 128) { row_m[tid] = -CUDART_INF_F; row_l[tid] = 0.0f; }
    __syncthreads();

    // lane-invariant ldmatrix address components
    const int a_row  = (lane & 7) + (lane & 8);        // + 16*i
    const int a_koff = ((lane >> 4) & 1) * 8;          // + 16*ks
    const int b_n    = (lane & 7) + ((lane >> 4) & 1) * 8;
    const int b_koff = (lane & 8);

    for (int t = 0; t < T1; t++) {
        const int kb = colbase + t * BN1;
        for (int idx = tid; idx < BN1 * 32; idx += NT) {
            const int r = idx >> 5, d2 = idx & 31;
            const float2 v = *(const float2*)&Km[(size_t)(kb + r) * D + d2 * 2];
            __nv_bfloat162 h2, l2; split2(v.x, v.y, h2, l2);
            *(__nv_bfloat162*)(smem + SKH + r * ROWB + d2 * 4) = h2;
            *(__nv_bfloat162*)(smem + SKL + r * ROWB + d2 * 4) = l2;
        }
        __syncthreads();

        float acc[2][8][4];
#pragma unroll
        for (int i = 0; i < 2; i++)
#pragma unroll
            for (int j = 0; j < 8; j++)
#pragma unroll
                for (int e = 0; e < 4; e++) acc[i][j][e] = 0.0f;

#pragma unroll
        for (int ks = 0; ks < 4; ks++) {
            uint32_t aH[2][4], aL[2][4];
#pragma unroll
            for (int i = 0; i < 2; i++) {
                const uint32_t ao =
                    (uint32_t)((wr + 16 * i + a_row) * ROWB + (ks * 16 + a_koff) * 2);
                ldsm_x4(aH[i], sb + SQH + ao);
                ldsm_x4(aL[i], sb + SQL + ao);
            }
#pragma unroll
            for (int jj = 0; jj < 4; jj++) {
                const uint32_t bo =
                    (uint32_t)((wc + jj * 16 + b_n) * ROWB + (ks * 16 + b_koff) * 2);
                uint32_t bh[4], bl[4];
                ldsm_x4(bh, sb + SKH + bo);
                ldsm_x4(bl, sb + SKL + bo);
#pragma unroll
                for (int i = 0; i < 2; i++)
#pragma unroll
                    for (int p = 0; p < 2; p++) {
                        float* c = acc[i][2 * jj + p];
                        mma_bf16(c, aH[i], bh[2 * p], bh[2 * p + 1]);
                        mma_bf16(c, aH[i], bl[2 * p], bl[2 * p + 1]);
                        mma_bf16(c, aL[i], bh[2 * p], bh[2 * p + 1]);
                    }
            }
        }

        // ---- epilogue: write raw S + per-warp row stats ----
        const int g = lane >> 2;
        const int tq = lane & 3;
#pragma unroll
        for (int i = 0; i < 2; i++) {
            const int ra = rowblk + wr + 16 * i + g;
            const int cb = kb + wc + 2 * tq;
#pragma unroll
            for (int j = 0; j < 8; j++) {
                *(float2*)&S[(size_t)ra * L + cb + 8 * j] =
                    make_float2(acc[i][j][0], acc[i][j][1]);
                *(float2*)&S[(size_t)(ra + 8) * L + cb + 8 * j] =
                    make_float2(acc[i][j][2], acc[i][j][3]);
            }
            float mxa = -CUDART_INF_F, mxb = -CUDART_INF_F;
#pragma unroll
            for (int j = 0; j < 8; j++) {
                mxa = fmaxf(mxa, fmaxf(acc[i][j][0], acc[i][j][1]));
                mxb = fmaxf(mxb, fmaxf(acc[i][j][2], acc[i][j][3]));
            }
            mxa = fmaxf(mxa, __shfl_xor_sync(0xffffffffu, mxa, 1));
            mxa = fmaxf(mxa, __shfl_xor_sync(0xffffffffu, mxa, 2));
            mxb = fmaxf(mxb, __shfl_xor_sync(0xffffffffu, mxb, 1));
            mxb = fmaxf(mxb, __shfl_xor_sync(0xffffffffu, mxb, 2));
            float sa = 0.0f, sbx = 0.0f;
#pragma unroll
            for (int j = 0; j < 8; j++) {
                sa  += __expf(acc[i][j][0] - mxa) + __expf(acc[i][j][1] - mxa);
                sbx += __expf(acc[i][j][2] - mxb) + __expf(acc[i][j][3] - mxb);
            }
            sa  += __shfl_xor_sync(0xffffffffu, sa, 1);
            sa  += __shfl_xor_sync(0xffffffffu, sa, 2);
            sbx += __shfl_xor_sync(0xffffffffu, sbx, 1);
            sbx += __shfl_xor_sync(0xffffffffu, sbx, 2);
            if (tq == 0) {
                const int r0 = wr + 16 * i + g;
                pm[cg * 128 + r0]     = mxa;  pl[cg * 128 + r0]     = sa;
                pm[cg * 128 + r0 + 8] = mxb;  pl[cg * 128 + r0 + 8] = sbx;
            }
        }
        __syncthreads();

        if (tid < 128) {     // combine the two col-groups + online update
            const float m0 = pm[tid], m1 = pm[128 + tid];
            const float m12 = fmaxf(m0, m1);
            const float l12 = pl[tid] * __expf(m0 - m12) +
                              pl[128 + tid] * __expf(m1 - m12);
            const float M = row_m[tid];
            const float nm = fmaxf(M, m12);
            row_l[tid] = row_l[tid] * __expf(M - nm) + l12 * __expf(m12 - nm);
            row_m[tid] = nm;
        }
        __syncthreads();
    }

    if (tid < 128) {
        g_mp[blockIdx.x * L + rowblk + tid] = row_m[tid];
        g_lp[blockIdx.x * L + rowblk + tid] = row_l[tid];
    }
}

// ---------------------------------------------------------------------------
// Combine per-chunk stats into final per-row (m, 1/l)
// ---------------------------------------------------------------------------
__global__ void combine_kernel() {
    const int row = blockIdx.x * 256 + threadIdx.x;
    float m = -CUDART_INF_F;
#pragma unroll
    for (int c = 0; c < NCH; c++) m = fmaxf(m, g_mp[c * L + row]);
    float l = 0.0f;
#pragma unroll
    for (int c = 0; c < NCH; c++)
        l += g_lp[c * L + row] * __expf(g_mp[c * L + row] - m);
    g_m[row]  = m;
    g_li[row] = 1.0f / l;
}

// ---------------------------------------------------------------------------
// Pass 2: normalize logits in place; partial O = P V via mma.sync
// warps: 8 x (16 rows); O stays in registers across all 16 chunk tiles
// ---------------------------------------------------------------------------
__global__ __launch_bounds__(NT, 2) void pass2_kernel(const float* __restrict__ V,
                                                      float* __restrict__ S) {
    extern __shared__ char smem[];
    const uint32_t sb = smem_to_u32(smem);
    const int tid  = threadIdx.x;
    const int lane = tid & 31;
    const int w    = tid >> 5;
    const int wr   = 16 * w;
    const int rowblk  = blockIdx.y * BM;
    const int colbase = blockIdx.x * CHUNK;

    float* m_s  = (float*)(smem + P2_STATS);
    float* li_s = m_s + 128;
    if (tid < 128) {
        m_s[tid]  = g_m[rowblk + tid];
        li_s[tid] = g_li[rowblk + tid];
    }

    float acc[8][4];
#pragma unroll
    for (int j = 0; j < 8; j++)
#pragma unroll
        for (int e = 0; e < 4; e++) acc[j][e] = 0.0f;

    const int a_row  = (lane & 7) + (lane & 8);
    const int a_koff = ((lane >> 4) & 1) * 8;
    const int bt_k   = (lane & 7) + (lane & 8);
    const int bt_n   = ((lane >> 4) & 1) * 8;

    __syncthreads();

    for (int t = 0; t < T2; t++) {
        const int kb = colbase + t * BN2;

        // P tile: read raw logits, softmax-normalize in place, split limbs
        for (int idx = tid; idx < BM * 16; idx += NT) {
            const int r = idx >> 4, c4 = idx & 15;
            float* sp = &S[(size_t)(rowblk + r) * L + kb + c4 * 4];
            const float4 s4 = *(const float4*)sp;
            const float mi = m_s[r], sc = li_s[r];
            float4 p4;
            p4.x = __expf(s4.x - mi) * sc;
            p4.y = __expf(s4.y - mi) * sc;
            p4.z = __expf(s4.z - mi) * sc;
            p4.w = __expf(s4.w - mi) * sc;
            *(float4*)sp = p4;
            __nv_bfloat162 h2, l2;
            split2(p4.x, p4.y, h2, l2);
            *(__nv_bfloat162*)(smem + SPH + r * ROWB + c4 * 8) = h2;
            *(__nv_bfloat162*)(smem + SPL + r * ROWB + c4 * 8) = l2;
            split2(p4.z, p4.w, h2, l2);
            *(__nv_bfloat162*)(smem + SPH + r * ROWB + c4 * 8 + 4) = h2;
            *(__nv_bfloat162*)(smem + SPL + r * ROWB + c4 * 8 + 4) = l2;
        }
        // V tile (natural [key][d] layout; ldmatrix.trans feeds B)
        for (int idx = tid; idx < BN2 * 16; idx += NT) {
            const int kk = idx >> 4, d4 = idx & 15;
            const float4 v = *(const float4*)&V[(size_t)(kb + kk) * D + d4 * 4];
            __nv_bfloat162 h2, l2;
            split2(v.x, v.y, h2, l2);
            *(__nv_bfloat162*)(smem + SVH + kk * ROWB + d4 * 8) = h2;
            *(__nv_bfloat162*)(smem + SVL + kk * ROWB + d4 * 8) = l2;
            split2(v.z, v.w, h2, l2);
            *(__nv_bfloat162*)(smem + SVH + kk * ROWB + d4 * 8 + 4) = h2;
            *(__nv_bfloat162*)(smem + SVL + kk * ROWB + d4 * 8 + 4) = l2;
        }
        __syncthreads();

#pragma unroll
        for (int ks = 0; ks < 4; ks++) {
            uint32_t aH[4], aL[4];
            const uint32_t ao =
                (uint32_t)((wr + a_row) * ROWB + (ks * 16 + a_koff) * 2);
            ldsm_x4(aH, sb + SPH + ao);
            ldsm_x4(aL, sb + SPL + ao);
#pragma unroll
            for (int jj = 0; jj < 4; jj++) {
                const uint32_t bo =
                    (uint32_t)((ks * 16 + bt_k) * ROWB + (jj * 16 + bt_n) * 2);
                uint32_t bh[4], bl[4];
                ldsm_x4_t(bh, sb + SVH + bo);
                ldsm_x4_t(bl, sb + SVL + bo);
#pragma unroll
                for (int p = 0; p < 2; p++) {
                    float* c = acc[2 * jj + p];
                    mma_bf16(c, aH, bh[2 * p], bh[2 * p + 1]);
                    mma_bf16(c, aH, bl[2 * p], bl[2 * p + 1]);
                    mma_bf16(c, aL, bh[2 * p], bh[2 * p + 1]);
                }
            }
        }
        __syncthreads();
    }

    // write partial O for this chunk
    const int g = lane >> 2, tq = lane & 3;
    const int ra = rowblk + wr + g;
    float* op0 = &g_opart[((size_t)blockIdx.x * L + ra) * D];
    float* op1 = &g_opart[((size_t)blockIdx.x * L + ra + 8) * D];
#pragma unroll
    for (int j = 0; j < 8; j++) {
        *(float2*)&op0[8 * j + 2 * tq] = make_float2(acc[j][0], acc[j][1]);
        *(float2*)&op1[8 * j + 2 * tq] = make_float2(acc[j][2], acc[j][3]);
    }
}

// ---------------------------------------------------------------------------
// Reduce the NCH partial O buffers into the final O
// ---------------------------------------------------------------------------
__global__ void reduce_o_kernel(float* __restrict__ O) {
    const size_t idx = (size_t)blockIdx.x * 256 + threadIdx.x;   // float4 index
    float4 s = make_float4(0.f, 0.f, 0.f, 0.f);
#pragma unroll
    for (int c = 0; c < NCH; c++) {
        const float4 v = *(const float4*)&g_opart[(size_t)c * L * D + idx * 4];
        s.x += v.x; s.y += v.y; s.z += v.z; s.w += v.w;
    }
    *(float4*)&O[idx * 4] = s;
}

extern "C" void kernel_launch(void* const* d_in, const int* in_sizes, int n_in,
                              void* d_out, int out_size) {
    const float* q = (const float*)d_in[0];
    const float* k = (const float*)d_in[1];
    const float* v = (const float*)d_in[2];

    float* out   = (float*)d_out;          // [L, D]
    float* score = out + (size_t)L * D;    // [L, L]

    cudaFuncSetAttribute(pass1_kernel,
                         cudaFuncAttributeMaxDynamicSharedMemorySize, P1_SMEM);
    cudaFuncSetAttribute(pass2_kernel,
                         cudaFuncAttributeMaxDynamicSharedMemorySize, P2_SMEM);

    dim3 grid(NCH, L / BM);
    pass1_kernel<<<grid, NT, P1_SMEM>>>(q, k, score);
    combine_kernel<<<L / 256, 256>>>();
    pass2_kernel<<<grid, NT, P2_SMEM>>>(v, score);
    reduce_o_kernel<<<(L * D / 4) / 256, 256>>>(out);
}

// round 6
// speedup vs baseline: 2.1612x; 1.7296x over previous
#include <cuda_runtime.h>
#include <cuda_bf16.h>
#include <math_constants.h>
#include <cstdint>

#define L     8192
#define D     64
#define BM    128            // query rows per CTA
#define NCH   8
#define CHUNK 1024           // L / NCH
#define BN1   128            // pass1 key-tile width
#define T1    8              // CHUNK / BN1
#define BN2   64             // pass2 key-tile width
#define T2    16             // CHUNK / BN2
#define NT    256
#define ROWB  144            // padded smem row stride in bytes (72 bf16)

// ---------------- scratch (__device__ globals; no allocation allowed) -------
__device__ float g_mp[NCH * L];
__device__ float g_lp[NCH * L];
__device__ float g_m[L];
__device__ float g_li[L];
__device__ float g_opart[(size_t)NCH * L * D];   // 16 MB partial O
// 2-limb bf16 versions of Q, K, V (prep kernel fills once)
__device__ __nv_bfloat16 gQh[L * D], gQl[L * D];
__device__ __nv_bfloat16 gKh[L * D], gKl[L * D];
__device__ __nv_bfloat16 gVh[L * D], gVl[L * D];

// ---------------- helpers ---------------------------------------------------
__device__ __forceinline__ uint32_t smem_to_u32(const void* p) {
    uint32_t a;
    asm("{ .reg .u64 t; cvta.to.shared.u64 t, %1; cvt.u32.u64 %0, t; }"
        : "=r"(a) : "l"(p));
    return a;
}
#define CP_ASYNC16(dst, src) \
    asm volatile("cp.async.cg.shared.global [%0], [%1], 16;" \
                 :: "r"(dst), "l"(src) : "memory")
#define CP_COMMIT() asm volatile("cp.async.commit_group;" ::: "memory")
#define CP_WAIT(n)  asm volatile("cp.async.wait_group %0;" :: "n"(n) : "memory")

__device__ __forceinline__ void ldsm_x4(uint32_t* r, uint32_t a) {
    asm volatile("ldmatrix.sync.aligned.m8n8.x4.shared.b16 {%0,%1,%2,%3}, [%4];"
                 : "=r"(r[0]), "=r"(r[1]), "=r"(r[2]), "=r"(r[3]) : "r"(a));
}
__device__ __forceinline__ void ldsm_x4_t(uint32_t* r, uint32_t a) {
    asm volatile("ldmatrix.sync.aligned.m8n8.x4.trans.shared.b16 {%0,%1,%2,%3}, [%4];"
                 : "=r"(r[0]), "=r"(r[1]), "=r"(r[2]), "=r"(r[3]) : "r"(a));
}
__device__ __forceinline__ void mma_bf16(float* c, const uint32_t* a,
                                         uint32_t b0, uint32_t b1) {
    asm volatile("mma.sync.aligned.m16n8k16.row.col.f32.bf16.bf16.f32 "
                 "{%0,%1,%2,%3}, {%4,%5,%6,%7}, {%8,%9}, {%0,%1,%2,%3};"
                 : "+f"(c[0]), "+f"(c[1]), "+f"(c[2]), "+f"(c[3])
                 : "r"(a[0]), "r"(a[1]), "r"(a[2]), "r"(a[3]), "r"(b0), "r"(b1));
}
__device__ __forceinline__ void split2(float x, float y,
                                       __nv_bfloat162& h2, __nv_bfloat162& l2) {
    __nv_bfloat16 hx = __float2bfloat16(x);
    __nv_bfloat16 hy = __float2bfloat16(y);
    h2.x = hx; h2.y = hy;
    l2.x = __float2bfloat16(x - __bfloat162float(hx));
    l2.y = __float2bfloat16(y - __bfloat162float(hy));
}

// pass1 smem byte offsets
#define SQH 0
#define SQL 18432
#define SK0 36864              // K buf b at SK0 + b*36864 (hi +0, lo +18432)
#define P1_STATS 110592
#define P1_SMEM  113664
// pass2 smem byte offsets
#define SPH 0
#define SPL 18432
#define SV0 36864              // V buf b at SV0 + b*18432 (hi +0, lo +9216)
#define P2_STATS 73728
#define P2_SMEM  74752

// ---------------------------------------------------------------------------
// Prep: split Q, K, V into bf16 hi/lo limb arrays
// ---------------------------------------------------------------------------
__global__ void prep_kernel(const float* __restrict__ Q,
                            const float* __restrict__ Km,
                            const float* __restrict__ V) {
    const int idx = blockIdx.x * 256 + threadIdx.x;    // float2 index
    const float* src; __nv_bfloat16 *dh, *dl;
    if (blockIdx.y == 0)      { src = Q;  dh = gQh; dl = gQl; }
    else if (blockIdx.y == 1) { src = Km; dh = gKh; dl = gKl; }
    else                      { src = V;  dh = gVh; dl = gVl; }
    const float2 v = *(const float2*)&src[idx * 2];
    __nv_bfloat162 h2, l2; split2(v.x, v.y, h2, l2);
    *(__nv_bfloat162*)&dh[idx * 2] = h2;
    *(__nv_bfloat162*)&dl[idx * 2] = l2;
}

// ---------------------------------------------------------------------------
// Pass 1: S = Q K^T raw logits (mma.sync, 2-limb) + per-chunk (m,l)
// warps: 4 row-groups x 2 col-groups; warp tile 32x64; K double-buffered cp.async
// ---------------------------------------------------------------------------
__global__ __launch_bounds__(NT, 2) void pass1_kernel(float* __restrict__ S) {
    extern __shared__ char smem[];
    const uint32_t sb = smem_to_u32(smem);
    const int tid  = threadIdx.x;
    const int lane = tid & 31;
    const int w    = tid >> 5;
    const int wr   = (w & 3) * 32;
    const int wc   = (w >> 2) * 64;
    const int cg   = w >> 2;
    const int rowblk  = blockIdx.y * BM;
    const int colbase = blockIdx.x * CHUNK;

    float* row_m = (float*)(smem + P1_STATS);       // [128]
    float* row_l = row_m + 128;                     // [128]
    float* pm    = row_l + 128;                     // [2][128]
    float* pl    = pm + 256;                        // [2][128]

    // prologue: Q limbs + K tile 0 via cp.async (group G0)
#pragma unroll
    for (int i = 0; i < 8; i++) {
        const int idx = tid + i * NT;                // 2048 chunks
        const int limb = idx >> 10, rem = idx & 1023;
        const int r = rem >> 3, c = rem & 7;
        const __nv_bfloat16* src =
            (limb ? gQl : gQh) + (size_t)(rowblk + r) * D + c * 8;
        CP_ASYNC16(sb + (limb ? SQL : SQH) + r * ROWB + c * 16, src);
    }
#pragma unroll
    for (int i = 0; i < 8; i++) {
        const int idx = tid + i * NT;
        const int limb = idx >> 10, rem = idx & 1023;
        const int r = rem >> 3, c = rem & 7;
        const __nv_bfloat16* src =
            (limb ? gKl : gKh) + (size_t)(colbase + r) * D + c * 8;
        CP_ASYNC16(sb + SK0 + limb * 18432 + r * ROWB + c * 16, src);
    }
    CP_COMMIT();
    if (tid < 128) { row_m[tid] = -CUDART_INF_F; row_l[tid] = 0.0f; }

    const int a_row  = (lane & 7) + (lane & 8);
    const int a_koff = ((lane >> 4) & 1) * 8;
    const int b_n    = (lane & 7) + ((lane >> 4) & 1) * 8;
    const int b_koff = (lane & 8);

    for (int t = 0; t < T1; t++) {
        if (t + 1 < T1) {       // prefetch next K tile into other buffer
            const int kb = colbase + (t + 1) * BN1;
            const uint32_t kd = sb + SK0 + ((t + 1) & 1) * 36864;
#pragma unroll
            for (int i = 0; i < 8; i++) {
                const int idx = tid + i * NT;
                const int limb = idx >> 10, rem = idx & 1023;
                const int r = rem >> 3, c = rem & 7;
                const __nv_bfloat16* src =
                    (limb ? gKl : gKh) + (size_t)(kb + r) * D + c * 8;
                CP_ASYNC16(kd + limb * 18432 + r * ROWB + c * 16, src);
            }
            CP_COMMIT();
            CP_WAIT(1);
        } else {
            CP_WAIT(0);
        }
        __syncthreads();

        const int kb = colbase + t * BN1;
        const uint32_t skh = sb + SK0 + (t & 1) * 36864;
        const uint32_t skl = skh + 18432;

        float acc[2][8][4];
#pragma unroll
        for (int i = 0; i < 2; i++)
#pragma unroll
            for (int j = 0; j < 8; j++)
#pragma unroll
                for (int e = 0; e < 4; e++) acc[i][j][e] = 0.0f;

#pragma unroll
        for (int ks = 0; ks < 4; ks++) {
            uint32_t aH[2][4], aL[2][4];
#pragma unroll
            for (int i = 0; i < 2; i++) {
                const uint32_t ao =
                    (uint32_t)((wr + 16 * i + a_row) * ROWB + (ks * 16 + a_koff) * 2);
                ldsm_x4(aH[i], sb + SQH + ao);
                ldsm_x4(aL[i], sb + SQL + ao);
            }
#pragma unroll
            for (int jj = 0; jj < 4; jj++) {
                const uint32_t bo =
                    (uint32_t)((wc + jj * 16 + b_n) * ROWB + (ks * 16 + b_koff) * 2);
                uint32_t bh[4], bl[4];
                ldsm_x4(bh, skh + bo);
                ldsm_x4(bl, skl + bo);
#pragma unroll
                for (int i = 0; i < 2; i++)
#pragma unroll
                    for (int p = 0; p < 2; p++) {
                        float* c = acc[i][2 * jj + p];
                        mma_bf16(c, aH[i], bh[2 * p], bh[2 * p + 1]);
                        mma_bf16(c, aH[i], bl[2 * p], bl[2 * p + 1]);
                        mma_bf16(c, aL[i], bh[2 * p], bh[2 * p + 1]);
                    }
            }
        }

        // epilogue: raw S + warp-level row stats
        const int g = lane >> 2, tq = lane & 3;
#pragma unroll
        for (int i = 0; i < 2; i++) {
            const int ra = rowblk + wr + 16 * i + g;
            const int cb = kb + wc + 2 * tq;
#pragma unroll
            for (int j = 0; j < 8; j++) {
                *(float2*)&S[(size_t)ra * L + cb + 8 * j] =
                    make_float2(acc[i][j][0], acc[i][j][1]);
                *(float2*)&S[(size_t)(ra + 8) * L + cb + 8 * j] =
                    make_float2(acc[i][j][2], acc[i][j][3]);
            }
            float mxa = -CUDART_INF_F, mxb = -CUDART_INF_F;
#pragma unroll
            for (int j = 0; j < 8; j++) {
                mxa = fmaxf(mxa, fmaxf(acc[i][j][0], acc[i][j][1]));
                mxb = fmaxf(mxb, fmaxf(acc[i][j][2], acc[i][j][3]));
            }
            mxa = fmaxf(mxa, __shfl_xor_sync(0xffffffffu, mxa, 1));
            mxa = fmaxf(mxa, __shfl_xor_sync(0xffffffffu, mxa, 2));
            mxb = fmaxf(mxb, __shfl_xor_sync(0xffffffffu, mxb, 1));
            mxb = fmaxf(mxb, __shfl_xor_sync(0xffffffffu, mxb, 2));
            float sa = 0.0f, sbx = 0.0f;
#pragma unroll
            for (int j = 0; j < 8; j++) {
                sa  += __expf(acc[i][j][0] - mxa) + __expf(acc[i][j][1] - mxa);
                sbx += __expf(acc[i][j][2] - mxb) + __expf(acc[i][j][3] - mxb);
            }
            sa  += __shfl_xor_sync(0xffffffffu, sa, 1);
            sa  += __shfl_xor_sync(0xffffffffu, sa, 2);
            sbx += __shfl_xor_sync(0xffffffffu, sbx, 1);
            sbx += __shfl_xor_sync(0xffffffffu, sbx, 2);
            if (tq == 0) {
                const int r0 = wr + 16 * i + g;
                pm[cg * 128 + r0]     = mxa;  pl[cg * 128 + r0]     = sa;
                pm[cg * 128 + r0 + 8] = mxb;  pl[cg * 128 + r0 + 8] = sbx;
            }
        }
        __syncthreads();

        if (tid < 128) {
            const float m0 = pm[tid], m1 = pm[128 + tid];
            const float m12 = fmaxf(m0, m1);
            const float l12 = pl[tid] * __expf(m0 - m12) +
                              pl[128 + tid] * __expf(m1 - m12);
            const float M = row_m[tid];
            const float nm = fmaxf(M, m12);
            row_l[tid] = row_l[tid] * __expf(M - nm) + l12 * __expf(m12 - nm);
            row_m[tid] = nm;
        }
        __syncthreads();
    }

    if (tid < 128) {
        g_mp[blockIdx.x * L + rowblk + tid] = row_m[tid];
        g_lp[blockIdx.x * L + rowblk + tid] = row_l[tid];
    }
}

// ---------------------------------------------------------------------------
// Combine per-chunk stats into final per-row (m, 1/l)
// ---------------------------------------------------------------------------
__global__ void combine_kernel() {
    const int row = blockIdx.x * 256 + threadIdx.x;
    float m = -CUDART_INF_F;
#pragma unroll
    for (int c = 0; c < NCH; c++) m = fmaxf(m, g_mp[c * L + row]);
    float l = 0.0f;
#pragma unroll
    for (int c = 0; c < NCH; c++)
        l += g_lp[c * L + row] * __expf(g_mp[c * L + row] - m);
    g_m[row]  = m;
    g_li[row] = 1.0f / l;
}

// ---------------------------------------------------------------------------
// Pass 2: normalize S in place; partial O = P V (pipelined: S LDGs for t+1
// issued before MMA(t); V limbs double-buffered cp.async)
// ---------------------------------------------------------------------------
__global__ __launch_bounds__(NT, 2) void pass2_kernel(float* __restrict__ S) {
    extern __shared__ char smem[];
    const uint32_t sb = smem_to_u32(smem);
    const int tid  = threadIdx.x;
    const int lane = tid & 31;
    const int w    = tid >> 5;
    const int wr   = 16 * w;
    const int rowblk  = blockIdx.y * BM;
    const int colbase = blockIdx.x * CHUNK;

    float* m_s  = (float*)(smem + P2_STATS);
    float* li_s = m_s + 128;
    if (tid < 128) {
        m_s[tid]  = g_m[rowblk + tid];
        li_s[tid] = g_li[rowblk + tid];
    }

    // prologue: V tile 0 (G0) + S tile 0 into regs
#pragma unroll
    for (int i = 0; i < 4; i++) {
        const int idx = tid + i * NT;                // 1024 chunks
        const int limb = idx >> 9, rem = idx & 511;
        const int r = rem >> 3, c = rem & 7;
        const __nv_bfloat16* src =
            (limb ? gVl : gVh) + (size_t)(colbase + r) * D + c * 8;
        CP_ASYNC16(sb + SV0 + limb * 9216 + r * ROWB + c * 16, src);
    }
    CP_COMMIT();

    float4 s4[8];
#pragma unroll
    for (int i = 0; i < 8; i++) {
        const int idx = i * NT + tid;
        const int r = idx >> 4, c4 = idx & 15;
        s4[i] = *(const float4*)&S[(size_t)(rowblk + r) * L + colbase + c4 * 4];
    }

    float acc[8][4];
#pragma unroll
    for (int j = 0; j < 8; j++)
#pragma unroll
        for (int e = 0; e < 4; e++) acc[j][e] = 0.0f;

    const int a_row  = (lane & 7) + (lane & 8);
    const int a_koff = ((lane >> 4) & 1) * 8;
    const int bt_k   = (lane & 7) + (lane & 8);
    const int bt_n   = ((lane >> 4) & 1) * 8;

    __syncthreads();   // stats visible

    for (int t = 0; t < T2; t++) {
        const int kb = colbase + t * BN2;

        if (t + 1 < T2) {   // prefetch next V tile
            const int kb1 = colbase + (t + 1) * BN2;
            const uint32_t vd = sb + SV0 + ((t + 1) & 1) * 18432;
#pragma unroll
            for (int i = 0; i < 4; i++) {
                const int idx = tid + i * NT;
                const int limb = idx >> 9, rem = idx & 511;
                const int r = rem >> 3, c = rem & 7;
                const __nv_bfloat16* src =
                    (limb ? gVl : gVh) + (size_t)(kb1 + r) * D + c * 8;
                CP_ASYNC16(vd + limb * 9216 + r * ROWB + c * 16, src);
            }
            CP_COMMIT();
        }

        // convert: s4 -> p, write normalized S back, split limbs to P smem
#pragma unroll
        for (int i = 0; i < 8; i++) {
            const int idx = i * NT + tid;
            const int r = idx >> 4, c4 = idx & 15;
            const float mi = m_s[r], sc = li_s[r];
            float4 p4;
            p4.x = __expf(s4[i].x - mi) * sc;
            p4.y = __expf(s4[i].y - mi) * sc;
            p4.z = __expf(s4[i].z - mi) * sc;
            p4.w = __expf(s4[i].w - mi) * sc;
            *(float4*)&S[(size_t)(rowblk + r) * L + kb + c4 * 4] = p4;
            __nv_bfloat162 h2, l2;
            split2(p4.x, p4.y, h2, l2);
            *(__nv_bfloat162*)(smem + SPH + r * ROWB + c4 * 8) = h2;
            *(__nv_bfloat162*)(smem + SPL + r * ROWB + c4 * 8) = l2;
            split2(p4.z, p4.w, h2, l2);
            *(__nv_bfloat162*)(smem + SPH + r * ROWB + c4 * 8 + 4) = h2;
            *(__nv_bfloat162*)(smem + SPL + r * ROWB + c4 * 8 + 4) = l2;
        }
        if (t + 1 < T2) { CP_WAIT(1); } else { CP_WAIT(0); }
        __syncthreads();

        // issue next S loads (complete during MMA)
        if (t + 1 < T2) {
            const int kb1 = colbase + (t + 1) * BN2;
#pragma unroll
            for (int i = 0; i < 8; i++) {
                const int idx = i * NT + tid;
                const int r = idx >> 4, c4 = idx & 15;
                s4[i] = *(const float4*)&S[(size_t)(rowblk + r) * L + kb1 + c4 * 4];
            }
        }

        const uint32_t svh = sb + SV0 + (t & 1) * 18432;
        const uint32_t svl = svh + 9216;
#pragma unroll
        for (int ks = 0; ks < 4; ks++) {
            uint32_t aH[4], aL[4];
            const uint32_t ao =
                (uint32_t)((wr + a_row) * ROWB + (ks * 16 + a_koff) * 2);
            ldsm_x4(aH, sb + SPH + ao);
            ldsm_x4(aL, sb + SPL + ao);
#pragma unroll
            for (int jj = 0; jj < 4; jj++) {
                const uint32_t bo =
                    (uint32_t)((ks * 16 + bt_k) * ROWB + (jj * 16 + bt_n) * 2);
                uint32_t bh[4], bl[4];
                ldsm_x4_t(bh, svh + bo);
                ldsm_x4_t(bl, svl + bo);
#pragma unroll
                for (int p = 0; p < 2; p++) {
                    float* c = acc[2 * jj + p];
                    mma_bf16(c, aH, bh[2 * p], bh[2 * p + 1]);
                    mma_bf16(c, aH, bl[2 * p], bl[2 * p + 1]);
                    mma_bf16(c, aL, bh[2 * p], bh[2 * p + 1]);
                }
            }
        }
        __syncthreads();
    }

    const int g = lane >> 2, tq = lane & 3;
    const int ra = rowblk + wr + g;
    float* op0 = &g_opart[((size_t)blockIdx.x * L + ra) * D];
    float* op1 = &g_opart[((size_t)blockIdx.x * L + ra + 8) * D];
#pragma unroll
    for (int j = 0; j < 8; j++) {
        *(float2*)&op0[8 * j + 2 * tq] = make_float2(acc[j][0], acc[j][1]);
        *(float2*)&op1[8 * j + 2 * tq] = make_float2(acc[j][2], acc[j][3]);
    }
}

// ---------------------------------------------------------------------------
// Reduce the NCH partial O buffers into the final O
// ---------------------------------------------------------------------------
__global__ void reduce_o_kernel(float* __restrict__ O) {
    const size_t idx = (size_t)blockIdx.x * 256 + threadIdx.x;   // float4 index
    float4 s = make_float4(0.f, 0.f, 0.f, 0.f);
#pragma unroll
    for (int c = 0; c < NCH; c++) {
        const float4 v = *(const float4*)&g_opart[(size_t)c * L * D + idx * 4];
        s.x += v.x; s.y += v.y; s.z += v.z; s.w += v.w;
    }
    *(float4*)&O[idx * 4] = s;
}

extern "C" void kernel_launch(void* const* d_in, const int* in_sizes, int n_in,
                              void* d_out, int out_size) {
    const float* q = (const float*)d_in[0];
    const float* k = (const float*)d_in[1];
    const float* v = (const float*)d_in[2];

    float* out   = (float*)d_out;          // [L, D]
    float* score = out + (size_t)L * D;    // [L, L]

    cudaFuncSetAttribute(pass1_kernel,
                         cudaFuncAttributeMaxDynamicSharedMemorySize, P1_SMEM);
    cudaFuncSetAttribute(pass2_kernel,
                         cudaFuncAttributeMaxDynamicSharedMemorySize, P2_SMEM);

    dim3 pgrid(L * D / (2 * 256), 3);
    prep_kernel<<<pgrid, 256>>>(q, k, v);

    dim3 grid(NCH, L / BM);
    pass1_kernel<<<grid, NT, P1_SMEM>>>(score);
    combine_kernel<<<L / 256, 256>>>();
    pass2_kernel<<<grid, NT, P2_SMEM>>>(score);
    reduce_o_kernel<<<(L * D / 4) / 256, 256>>>(out);
}

// round 7
// speedup vs baseline: 2.3053x; 1.0667x over previous
#include <cuda_runtime.h>
#include <cuda_bf16.h>
#include <math_constants.h>
#include <cstdint>

#define L     8192
#define D     64
#define BM    128            // query rows per CTA
#define NCH   8
#define CHUNK 1024           // L / NCH
#define BN1   64             // pass1 key-tile width
#define T1    16             // CHUNK / BN1
#define BN2   64             // pass2 key-tile width
#define T2    16             // CHUNK / BN2
#define NT    256

// ---------------- scratch (__device__ globals; no allocation allowed) -------
__device__ float g_mp[NCH * L];
__device__ float g_lp[NCH * L];
__device__ float g_m[L];
__device__ float g_li[L];
// 2-limb bf16 versions of Q, K, V (prep kernel fills once)
__device__ __nv_bfloat16 gQh[L * D], gQl[L * D];
__device__ __nv_bfloat16 gKh[L * D], gKl[L * D];
__device__ __nv_bfloat16 gVh[L * D], gVl[L * D];

// ---------------- helpers ---------------------------------------------------
__device__ __forceinline__ uint32_t smem_to_u32(const void* p) {
    uint32_t a;
    asm("{ .reg .u64 t; cvta.to.shared.u64 t, %1; cvt.u32.u64 %0, t; }"
        : "=r"(a) : "l"(p));
    return a;
}
#define CP_ASYNC16(dst, src) \
    asm volatile("cp.async.cg.shared.global [%0], [%1], 16;" \
                 :: "r"(dst), "l"(src) : "memory")
#define CP_COMMIT() asm volatile("cp.async.commit_group;" ::: "memory")
#define CP_WAIT(n)  asm volatile("cp.async.wait_group %0;" :: "n"(n) : "memory")

__device__ __forceinline__ void ldsm_x4(uint32_t* r, uint32_t a) {
    asm volatile("ldmatrix.sync.aligned.m8n8.x4.shared.b16 {%0,%1,%2,%3}, [%4];"
                 : "=r"(r[0]), "=r"(r[1]), "=r"(r[2]), "=r"(r[3]) : "r"(a));
}
__device__ __forceinline__ void ldsm_x4_t(uint32_t* r, uint32_t a) {
    asm volatile("ldmatrix.sync.aligned.m8n8.x4.trans.shared.b16 {%0,%1,%2,%3}, [%4];"
                 : "=r"(r[0]), "=r"(r[1]), "=r"(r[2]), "=r"(r[3]) : "r"(a));
}
__device__ __forceinline__ void mma_bf16(float* c, const uint32_t* a,
                                         uint32_t b0, uint32_t b1) {
    asm volatile("mma.sync.aligned.m16n8k16.row.col.f32.bf16.bf16.f32 "
                 "{%0,%1,%2,%3}, {%4,%5,%6,%7}, {%8,%9}, {%0,%1,%2,%3};"
                 : "+f"(c[0]), "+f"(c[1]), "+f"(c[2]), "+f"(c[3])
                 : "r"(a[0]), "r"(a[1]), "r"(a[2]), "r"(a[3]), "r"(b0), "r"(b1));
}
__device__ __forceinline__ void split2(float x, float y,
                                       __nv_bfloat162& h2, __nv_bfloat162& l2) {
    __nv_bfloat16 hx = __float2bfloat16(x);
    __nv_bfloat16 hy = __float2bfloat16(y);
    h2.x = hx; h2.y = hy;
    l2.x = __float2bfloat16(x - __bfloat162float(hx));
    l2.y = __float2bfloat16(y - __bfloat162float(hy));
}
// SW128 swizzle: 128B rows, 16B chunks; chunk c of row r lives at c^(r&7)
__device__ __forceinline__ uint32_t swo(int r, int c16) {
    return (uint32_t)(r * 128 + ((c16 ^ (r & 7)) << 4));
}

// pass1 smem byte offsets (swizzled 128B rows)
#define SQH 0
#define SQL 16384
#define SK0 32768              // buf b at SK0 + b*16384 (hi +0, lo +8192)
#define P1_STATS 65536
#define P1_SMEM  (65536 + 3072)
// pass2 smem byte offsets
#define SPH 0
#define SPL 16384
#define SV0 32768              // buf b at SV0 + b*16384 (hi +0, lo +8192)
#define P2_STATS 65536
#define P2_SMEM  (65536 + 1024)

// ---------------------------------------------------------------------------
// Prep: split Q, K, V into bf16 hi/lo limb arrays
// ---------------------------------------------------------------------------
__global__ void prep_kernel(const float* __restrict__ Q,
                            const float* __restrict__ Km,
                            const float* __restrict__ V) {
    const int idx = blockIdx.x * 256 + threadIdx.x;    // float2 index
    const float* src; __nv_bfloat16 *dh, *dl;
    if (blockIdx.y == 0)      { src = Q;  dh = gQh; dl = gQl; }
    else if (blockIdx.y == 1) { src = Km; dh = gKh; dl = gKl; }
    else                      { src = V;  dh = gVh; dl = gVl; }
    const float2 v = *(const float2*)&src[idx * 2];
    __nv_bfloat162 h2, l2; split2(v.x, v.y, h2, l2);
    *(__nv_bfloat162*)&dh[idx * 2] = h2;
    *(__nv_bfloat162*)&dl[idx * 2] = l2;
}

__global__ void zero_o_kernel(float* __restrict__ O) {
    const int idx = blockIdx.x * 256 + threadIdx.x;
    *(float4*)&O[idx * 4] = make_float4(0.f, 0.f, 0.f, 0.f);
}

// ---------------------------------------------------------------------------
// Pass 1: S = Q K^T raw logits (mma.sync, 2-limb) + per-chunk (m,l)
// warps: 4 row x 2 col groups; warp tile 32x32; K double-buffered cp.async
// ---------------------------------------------------------------------------
__global__ __launch_bounds__(NT, 3) void pass1_kernel(float* __restrict__ S) {
    extern __shared__ char smem[];
    const uint32_t sb = smem_to_u32(smem);
    const int tid  = threadIdx.x;
    const int lane = tid & 31;
    const int w    = tid >> 5;
    const int wr   = (w & 3) * 32;
    const int wc   = (w >> 2) * 32;
    const int cg   = w >> 2;
    const int rowblk  = blockIdx.y * BM;
    const int colbase = blockIdx.x * CHUNK;

    float* row_m = (float*)(smem + P1_STATS);       // [128]
    float* row_l = row_m + 128;                     // [128]
    float* pm    = row_l + 128;                     // [2][128]
    float* pl    = pm + 256;                        // [2][128]

    // prologue: Q limbs + K tile 0 via cp.async (one group)
#pragma unroll
    for (int i = 0; i < 8; i++) {
        const int idx = tid + i * NT;                // 2048 chunks
        const int limb = idx >> 10, rem = idx & 1023;
        const int r = rem >> 3, c = rem & 7;
        const __nv_bfloat16* src =
            (limb ? gQl : gQh) + (size_t)(rowblk + r) * D + c * 8;
        CP_ASYNC16(sb + (limb ? SQL : SQH) + swo(r, c), src);
    }
#pragma unroll
    for (int i = 0; i < 4; i++) {
        const int idx = tid + i * NT;                // 1024 chunks
        const int limb = idx >> 9, rem = idx & 511;
        const int r = rem >> 3, c = rem & 7;
        const __nv_bfloat16* src =
            (limb ? gKl : gKh) + (size_t)(colbase + r) * D + c * 8;
        CP_ASYNC16(sb + SK0 + limb * 8192 + swo(r, c), src);
    }
    CP_COMMIT();
    if (tid < 128) { row_m[tid] = -CUDART_INF_F; row_l[tid] = 0.0f; }

    const int a_row = (lane & 7) + (lane & 8);
    const int a_c   = (lane >> 4) & 1;
    const int b_n   = (lane & 7) + ((lane >> 4) & 1) * 8;
    const int b_c   = (lane >> 3) & 1;

    for (int t = 0; t < T1; t++) {
        if (t + 1 < T1) {       // prefetch next K tile
            const int kb = colbase + (t + 1) * BN1;
            const uint32_t kd = sb + SK0 + ((t + 1) & 1) * 16384;
#pragma unroll
            for (int i = 0; i < 4; i++) {
                const int idx = tid + i * NT;
                const int limb = idx >> 9, rem = idx & 511;
                const int r = rem >> 3, c = rem & 7;
                const __nv_bfloat16* src =
                    (limb ? gKl : gKh) + (size_t)(kb + r) * D + c * 8;
                CP_ASYNC16(kd + limb * 8192 + swo(r, c), src);
            }
            CP_COMMIT();
            CP_WAIT(1);
        } else {
            CP_WAIT(0);
        }
        __syncthreads();

        const int kb = colbase + t * BN1;
        const uint32_t skh = sb + SK0 + (t & 1) * 16384;
        const uint32_t skl = skh + 8192;

        float acc[2][4][4];
#pragma unroll
        for (int i = 0; i < 2; i++)
#pragma unroll
            for (int j = 0; j < 4; j++)
#pragma unroll
                for (int e = 0; e < 4; e++) acc[i][j][e] = 0.0f;

#pragma unroll
        for (int ks = 0; ks < 4; ks++) {
            uint32_t aH[2][4], aL[2][4];
#pragma unroll
            for (int i = 0; i < 2; i++) {
                const int ar = wr + 16 * i + a_row;
                const uint32_t ao = swo(ar, ks * 2 + a_c);
                ldsm_x4(aH[i], sb + SQH + ao);
                ldsm_x4(aL[i], sb + SQL + ao);
            }
#pragma unroll
            for (int jj = 0; jj < 2; jj++) {
                const int br = wc + jj * 16 + b_n;
                const uint32_t bo = swo(br, ks * 2 + b_c);
                uint32_t bh[4], bl[4];
                ldsm_x4(bh, skh + bo);
                ldsm_x4(bl, skl + bo);
#pragma unroll
                for (int i = 0; i < 2; i++)
#pragma unroll
                    for (int p = 0; p < 2; p++) {
                        float* c = acc[i][2 * jj + p];
                        mma_bf16(c, aH[i], bh[2 * p], bh[2 * p + 1]);
                        mma_bf16(c, aH[i], bl[2 * p], bl[2 * p + 1]);
                        mma_bf16(c, aL[i], bh[2 * p], bh[2 * p + 1]);
                    }
            }
        }

        // epilogue: raw S + warp-level row stats (32 cols per warp)
        const int g = lane >> 2, tq = lane & 3;
#pragma unroll
        for (int i = 0; i < 2; i++) {
            const int ra = rowblk + wr + 16 * i + g;
            const int cb = kb + wc + 2 * tq;
#pragma unroll
            for (int j = 0; j < 4; j++) {
                *(float2*)&S[(size_t)ra * L + cb + 8 * j] =
                    make_float2(acc[i][j][0], acc[i][j][1]);
                *(float2*)&S[(size_t)(ra + 8) * L + cb + 8 * j] =
                    make_float2(acc[i][j][2], acc[i][j][3]);
            }
            float mxa = -CUDART_INF_F, mxb = -CUDART_INF_F;
#pragma unroll
            for (int j = 0; j < 4; j++) {
                mxa = fmaxf(mxa, fmaxf(acc[i][j][0], acc[i][j][1]));
                mxb = fmaxf(mxb, fmaxf(acc[i][j][2], acc[i][j][3]));
            }
            mxa = fmaxf(mxa, __shfl_xor_sync(0xffffffffu, mxa, 1));
            mxa = fmaxf(mxa, __shfl_xor_sync(0xffffffffu, mxa, 2));
            mxb = fmaxf(mxb, __shfl_xor_sync(0xffffffffu, mxb, 1));
            mxb = fmaxf(mxb, __shfl_xor_sync(0xffffffffu, mxb, 2));
            float sa = 0.0f, sbx = 0.0f;
#pragma unroll
            for (int j = 0; j < 4; j++) {
                sa  += __expf(acc[i][j][0] - mxa) + __expf(acc[i][j][1] - mxa);
                sbx += __expf(acc[i][j][2] - mxb) + __expf(acc[i][j][3] - mxb);
            }
            sa  += __shfl_xor_sync(0xffffffffu, sa, 1);
            sa  += __shfl_xor_sync(0xffffffffu, sa, 2);
            sbx += __shfl_xor_sync(0xffffffffu, sbx, 1);
            sbx += __shfl_xor_sync(0xffffffffu, sbx, 2);
            if (tq == 0) {
                const int r0 = wr + 16 * i + g;
                pm[cg * 128 + r0]     = mxa;  pl[cg * 128 + r0]     = sa;
                pm[cg * 128 + r0 + 8] = mxb;  pl[cg * 128 + r0 + 8] = sbx;
            }
        }
        __syncthreads();

        if (tid < 128) {
            const float m0 = pm[tid], m1 = pm[128 + tid];
            const float m12 = fmaxf(m0, m1);
            const float l12 = pl[tid] * __expf(m0 - m12) +
                              pl[128 + tid] * __expf(m1 - m12);
            const float M = row_m[tid];
            const float nm = fmaxf(M, m12);
            row_l[tid] = row_l[tid] * __expf(M - nm) + l12 * __expf(m12 - nm);
            row_m[tid] = nm;
        }
        __syncthreads();
    }

    if (tid < 128) {
        g_mp[blockIdx.x * L + rowblk + tid] = row_m[tid];
        g_lp[blockIdx.x * L + rowblk + tid] = row_l[tid];
    }
}

// ---------------------------------------------------------------------------
// Combine per-chunk stats into final per-row (m, 1/l)
// ---------------------------------------------------------------------------
__global__ void combine_kernel() {
    const int row = blockIdx.x * 256 + threadIdx.x;
    float m = -CUDART_INF_F;
#pragma unroll
    for (int c = 0; c < NCH; c++) m = fmaxf(m, g_mp[c * L + row]);
    float l = 0.0f;
#pragma unroll
    for (int c = 0; c < NCH; c++)
        l += g_lp[c * L + row] * __expf(g_mp[c * L + row] - m);
    g_m[row]  = m;
    g_li[row] = 1.0f / l;
}

// ---------------------------------------------------------------------------
// Pass 2: normalize S in place; O += P V via mma.sync + atomics.
// Next-tile S loads interleaved into the convert loop (early issue);
// V limbs double-buffered cp.async.
// ---------------------------------------------------------------------------
__global__ __launch_bounds__(NT, 2) void pass2_kernel(float* __restrict__ S,
                                                      float* __restrict__ O) {
    extern __shared__ char smem[];
    const uint32_t sb = smem_to_u32(smem);
    const int tid  = threadIdx.x;
    const int lane = tid & 31;
    const int w    = tid >> 5;
    const int wr   = 16 * w;
    const int rowblk  = blockIdx.y * BM;
    const int colbase = blockIdx.x * CHUNK;

    float* m_s  = (float*)(smem + P2_STATS);
    float* li_s = m_s + 128;
    if (tid < 128) {
        m_s[tid]  = g_m[rowblk + tid];
        li_s[tid] = g_li[rowblk + tid];
    }

    // prologue: V tile 0 + S tile 0 into regs
#pragma unroll
    for (int i = 0; i < 4; i++) {
        const int idx = tid + i * NT;                // 1024 chunks
        const int limb = idx >> 9, rem = idx & 511;
        const int r = rem >> 3, c = rem & 7;
        const __nv_bfloat16* src =
            (limb ? gVl : gVh) + (size_t)(colbase + r) * D + c * 8;
        CP_ASYNC16(sb + SV0 + limb * 8192 + swo(r, c), src);
    }
    CP_COMMIT();

    float4 s4[8];
#pragma unroll
    for (int i = 0; i < 8; i++) {
        const int idx = i * NT + tid;
        const int r = idx >> 4, c4 = idx & 15;
        s4[i] = *(const float4*)&S[(size_t)(rowblk + r) * L + colbase + c4 * 4];
    }

    float acc[8][4];
#pragma unroll
    for (int j = 0; j < 8; j++)
#pragma unroll
        for (int e = 0; e < 4; e++) acc[j][e] = 0.0f;

    const int a_row = (lane & 7) + (lane & 8);
    const int a_c   = (lane >> 4) & 1;
    const int bt_k  = (lane & 7) + (lane & 8);
    const int bt_c  = (lane >> 4) & 1;          // bt_n>>3

    __syncthreads();   // stats visible

    for (int t = 0; t < T2; t++) {
        const int kb = colbase + t * BN2;

        if (t + 1 < T2) {   // prefetch next V tile
            const int kb1 = colbase + (t + 1) * BN2;
            const uint32_t vd = sb + SV0 + ((t + 1) & 1) * 16384;
#pragma unroll
            for (int i = 0; i < 4; i++) {
                const int idx = tid + i * NT;
                const int limb = idx >> 9, rem = idx & 511;
                const int r = rem >> 3, c = rem & 7;
                const __nv_bfloat16* src =
                    (limb ? gVl : gVh) + (size_t)(kb1 + r) * D + c * 8;
                CP_ASYNC16(vd + limb * 8192 + swo(r, c), src);
            }
            CP_COMMIT();
        }

        // convert + interleaved next-tile S reloads (early LDG issue)
#pragma unroll
        for (int i = 0; i < 8; i++) {
            const int idx = i * NT + tid;
            const int r = idx >> 4, c4 = idx & 15;
            const float mi = m_s[r], sc = li_s[r];
            float4 p4;
            p4.x = __expf(s4[i].x - mi) * sc;
            p4.y = __expf(s4[i].y - mi) * sc;
            p4.z = __expf(s4[i].z - mi) * sc;
            p4.w = __expf(s4[i].w - mi) * sc;
            if (t + 1 < T2)   // reload immediately after consumption
                s4[i] = *(const float4*)&S[(size_t)(rowblk + r) * L +
                                           kb + BN2 + c4 * 4];
            *(float4*)&S[(size_t)(rowblk + r) * L + kb + c4 * 4] = p4;
            const uint32_t off = swo(r, c4 >> 1) + (c4 & 1) * 8;
            __nv_bfloat162 h2, l2;
            split2(p4.x, p4.y, h2, l2);
            *(__nv_bfloat162*)(smem + SPH + off) = h2;
            *(__nv_bfloat162*)(smem + SPL + off) = l2;
            split2(p4.z, p4.w, h2, l2);
            *(__nv_bfloat162*)(smem + SPH + off + 4) = h2;
            *(__nv_bfloat162*)(smem + SPL + off + 4) = l2;
        }
        if (t + 1 < T2) { CP_WAIT(1); } else { CP_WAIT(0); }
        __syncthreads();

        const uint32_t svh = sb + SV0 + (t & 1) * 16384;
        const uint32_t svl = svh + 8192;
#pragma unroll
        for (int ks = 0; ks < 4; ks++) {
            uint32_t aH[4], aL[4];
            const int ar = wr + a_row;
            const uint32_t ao = swo(ar, ks * 2 + a_c);
            ldsm_x4(aH, sb + SPH + ao);
            ldsm_x4(aL, sb + SPL + ao);
#pragma unroll
            for (int jj = 0; jj < 4; jj++) {
                const int kr = ks * 16 + bt_k;
                const uint32_t bo = swo(kr, 2 * jj + bt_c);
                uint32_t bh[4], bl[4];
                ldsm_x4_t(bh, svh + bo);
                ldsm_x4_t(bl, svl + bo);
#pragma unroll
                for (int p = 0; p < 2; p++) {
                    float* c = acc[2 * jj + p];
                    mma_bf16(c, aH, bh[2 * p], bh[2 * p + 1]);
                    mma_bf16(c, aH, bl[2 * p], bl[2 * p + 1]);
                    mma_bf16(c, aL, bh[2 * p], bh[2 * p + 1]);
                }
            }
        }
        __syncthreads();
    }

    // epilogue: atomic-accumulate partial O (O pre-zeroed)
    const int g = lane >> 2, tq = lane & 3;
    const int ra = rowblk + wr + g;
#pragma unroll
    for (int j = 0; j < 8; j++) {
        atomicAdd(&O[(size_t)ra * D + 8 * j + 2 * tq],     acc[j][0]);
        atomicAdd(&O[(size_t)ra * D + 8 * j + 2 * tq + 1], acc[j][1]);
        atomicAdd(&O[(size_t)(ra + 8) * D + 8 * j + 2 * tq],     acc[j][2]);
        atomicAdd(&O[(size_t)(ra + 8) * D + 8 * j + 2 * tq + 1], acc[j][3]);
    }
}

extern "C" void kernel_launch(void* const* d_in, const int* in_sizes, int n_in,
                              void* d_out, int out_size) {
    const float* q = (const float*)d_in[0];
    const float* k = (const float*)d_in[1];
    const float* v = (const float*)d_in[2];

    float* out   = (float*)d_out;          // [L, D]
    float* score = out + (size_t)L * D;    // [L, L]

    cudaFuncSetAttribute(pass1_kernel,
                         cudaFuncAttributeMaxDynamicSharedMemorySize, P1_SMEM);
    cudaFuncSetAttribute(pass2_kernel,
                         cudaFuncAttributeMaxDynamicSharedMemorySize, P2_SMEM);

    dim3 pgrid(L * D / (2 * 256), 3);
    prep_kernel<<<pgrid, 256>>>(q, k, v);
    zero_o_kernel<<<L * D / 4 / 256, 256>>>(out);

    dim3 grid(NCH, L / BM);
    pass1_kernel<<<grid, NT, P1_SMEM>>>(score);
    combine_kernel<<<L / 256, 256>>>();
    pass2_kernel<<<grid, NT, P2_SMEM>>>(score, out);
}